// round 5
// baseline (speedup 1.0000x reference)
#include <cuda_runtime.h>
#include <cuda_fp16.h>
#include <cstdint>

// ============================================================================
// x[32,256,56,56] -> shift2d -> 1x1 conv W[256,256] -> BN -> ReLU
// GEMM: M = 100352 pixels, N = 256, K = 256.
// mma.sync.m16n8k16 fp16 / fp32 accum, single-pass fp16 (BN folded into W).
// 256 threads, 2 CTAs/SM. Fragment loads via ldmatrix.x4.
// ============================================================================
#define CIN    256
#define COUT   256
#define HH     56
#define WWD    56
#define HWSZ   3136
#define NPIX   100352          // 32*3136
#define CTA_M  64
#define GRID   (NPIX / CTA_M)  // 1568
#define KCH    64
#define NCHUNK 4

// SMEM layout (bytes):
//   [0,1024)         bias[256] f32
//   [1024, +18432)   A[buf][64 rows][144B]  (row stride 36 words, conflict-free)
//   [19456, +73728)  B[buf][256 rows][144B]
#define OFF_A      1024
#define OFF_B      19456
#define A_BUF_W    (64 * 36)          // words per A buffer
#define A_BUF_BY   (64 * 144)        // 9216 bytes
#define B_BUF_BY   (256 * 144)       // 36864 bytes
#define SMEM_BYTES 93184

// device-global scratch (sanctioned)
__device__ __half g_w[COUT * CIN];    // W[o][c] * inv[o], fp16, k-contiguous
__device__ float  g_bias[COUT];

#define DEVINL __device__ __forceinline__

DEVINL uint32_t smem_u32(const void* p) {
    uint32_t a;
    asm("{ .reg .u64 t; cvta.to.shared.u64 t, %1; cvt.u32.u64 %0, t; }"
        : "=r"(a) : "l"(p));
    return a;
}

#define CP_ASYNC16(dst_u32, src_ptr) \
    asm volatile("cp.async.cg.shared.global [%0], [%1], 16;" \
        :: "r"(dst_u32), "l"(src_ptr) : "memory")
#define CP_COMMIT() asm volatile("cp.async.commit_group;" ::: "memory")
#define CP_WAIT0()  asm volatile("cp.async.wait_group 0;"  ::: "memory")

#define MMA16816(d, a0, a1, a2, a3, b0, b1) \
    asm volatile("mma.sync.aligned.m16n8k16.row.col.f32.f16.f16.f32 " \
        "{%0,%1,%2,%3}, {%4,%5,%6,%7}, {%8,%9}, {%0,%1,%2,%3};" \
        : "+f"((d)[0]), "+f"((d)[1]), "+f"((d)[2]), "+f"((d)[3]) \
        : "r"(a0), "r"(a1), "r"(a2), "r"(a3), "r"(b0), "r"(b1))

#define LDSM4(r, addr) \
    asm volatile("ldmatrix.sync.aligned.m8n8.x4.shared.b16 {%0,%1,%2,%3}, [%4];" \
        : "=r"((r)[0]), "=r"((r)[1]), "=r"((r)[2]), "=r"((r)[3]) : "r"(addr))

// channel -> shift direction index (group starts: 0,51,102,153,204)
DEVINL int ch_dir(int c) {
    return (c >= 204) ? 4 : (c >= 153) ? 3 : (c >= 102) ? 2 : (c >= 51) ? 1 : 0;
}

// ============================================================================
// prep: fold BN scale into W, convert to fp16; compute bias. 256 blk x 64 thr.
// ============================================================================
__global__ void prep_kernel(const float* __restrict__ pw,
                            const float* __restrict__ gamma,
                            const float* __restrict__ beta,
                            const float* __restrict__ rmean,
                            const float* __restrict__ rvar)
{
    const int o  = blockIdx.x;
    const int c4 = threadIdx.x;            // 0..63, handles 4 channels
    const float inv_o = gamma[o] * rsqrtf(rvar[o] + 1e-5f);
    float4 v = *reinterpret_cast<const float4*>(pw + (size_t)o * CIN + c4 * 4);
    __half2 h01 = __floats2half2_rn(v.x * inv_o, v.y * inv_o);
    __half2 h23 = __floats2half2_rn(v.z * inv_o, v.w * inv_o);
    *reinterpret_cast<__half2*>(g_w + (size_t)o * CIN + c4 * 4)     = h01;
    *reinterpret_cast<__half2*>(g_w + (size_t)o * CIN + c4 * 4 + 2) = h23;
    if (o == 0) {
        #pragma unroll
        for (int j = 0; j < 4; ++j) {
            int c = c4 * 4 + j;
            float inv_c = gamma[c] * rsqrtf(rvar[c] + 1e-5f);
            g_bias[c] = beta[c] - rmean[c] * inv_c;
        }
    }
}

// ============================================================================
// main kernel: 256 threads, warp grid 2(M) x 4(N); warp tile 32 x 64.
// ============================================================================
__global__ void __launch_bounds__(256, 2)
shiftconv_kernel(const float* __restrict__ x, float* __restrict__ out)
{
    extern __shared__ char smem[];
    float*    sbias = (float*)smem;
    uint32_t* sA    = (uint32_t*)(smem + OFF_A);
    uint32_t* sB    = (uint32_t*)(smem + OFF_B);

    const int tid  = threadIdx.x;
    const int warp = tid >> 5;
    const int lane = tid & 31;
    const int gr   = lane >> 2;
    const int lq   = lane & 3;

    const int warp_px = (warp & 1) * 32;   // M offset within CTA
    const int warp_n  = (warp >> 1) * 64;  // N offset

    sbias[tid] = g_bias[tid];

    const uint32_t sA_u32 = smem_u32(sA);
    const uint32_t sB_u32 = smem_u32(sB);

    // ---- ldmatrix per-lane base addresses (computed once) ------------------
    // A x4 tiles: t0 rows0-7/k0-7, t1 rows8-15/k0-7, t2 rows0-7/k8-15, t3 rows8-15/k8-15
    uint32_t a_addr[2];
    {
        const int arow = (lane & 15);               // rows 0..15 of the 16-row tile
        const int acol = (lane >> 4) * 16;          // 0 or 16 bytes (k 0-7 vs 8-15)
        #pragma unroll
        for (int mi = 0; mi < 2; ++mi)
            a_addr[mi] = sA_u32 + (uint32_t)(warp_px + mi * 16 + arow) * 144 + acol;
    }
    // B x4 tiles: t0 n0-7/k0-7(b0 g0), t1 n0-7/k8-15(b1 g0), t2 n8-15/k0-7, t3 n8-15/k8-15
    uint32_t b_addr[4];
    {
        const int grp  = lane >> 3;                                   // 0..3
        const int nrow = lane - ((grp == 1 || grp == 2) ? 8 : (grp == 3) ? 16 : 0);
        const int bcol = (grp & 1) * 16;                              // bytes
        #pragma unroll
        for (int f16 = 0; f16 < 4; ++f16)
            b_addr[f16] = sB_u32 + (uint32_t)(warp_n + f16 * 16 + nrow) * 144 + bcol;
    }

    // ---- A staging thread mapping ------------------------------------------
    const int pxl = tid & 63;
    const int c2  = tid >> 6;
    const int P   = blockIdx.x * CTA_M + pxl;
    const int bb  = P / HWSZ;
    const int rr  = P - bb * HWSZ;
    const int hh  = rr / WWD;
    const int ww  = rr - hh * WWD;
    const float* xb = x + (size_t)bb * CIN * HWSZ;

    int  offs[5];
    bool vald[5];
    {
        const int dxs[5] = {0, 1, -1, 0, 0};
        const int dys[5] = {0, 0, 0, 1, -1};
        #pragma unroll
        for (int d5 = 0; d5 < 5; ++d5) {
            int hs = hh - dys[d5], ws = ww - dxs[d5];
            vald[d5] = ((unsigned)hs < HH) && ((unsigned)ws < WWD);
            offs[d5] = hs * WWD + ws;
        }
    }

    // B staging mapping
    const int bu = tid & 7;
    const int bn = tid >> 3;

    float vstage[16];

    auto ldg_A = [&](int chunk) {
        const int c0 = chunk * KCH;
        #pragma unroll
        for (int it = 0; it < 8; ++it) {
            const int ch0 = c0 + 2 * (c2 * 8 + it);
            const int d0  = ch_dir(ch0);
            const int d1  = ch_dir(ch0 + 1);
            vstage[2*it]   = vald[d0] ? __ldg(xb + (size_t)ch0       * HWSZ + offs[d0]) : 0.0f;
            vstage[2*it+1] = vald[d1] ? __ldg(xb + (size_t)(ch0 + 1) * HWSZ + offs[d1]) : 0.0f;
        }
    };

    auto sts_A = [&](int buf) {
        uint32_t* Ab = sA + buf * A_BUF_W;
        #pragma unroll
        for (int it = 0; it < 8; ++it) {
            const int pi = c2 * 8 + it;
            __half2 h = __floats2half2_rn(vstage[2*it], vstage[2*it+1]);
            Ab[pxl * 36 + pi] = *reinterpret_cast<uint32_t*>(&h);
        }
    };

    auto cp_B = [&](int chunk, int buf) {
        const int c0 = chunk * KCH;
        #pragma unroll
        for (int itn = 0; itn < 8; ++itn) {
            const int n = bn + 32 * itn;
            const uint32_t dst = sB_u32 + (uint32_t)(buf * 256 + n) * 144 + bu * 16;
            const __half* src = g_w + (size_t)n * CIN + c0 + bu * 8;
            CP_ASYNC16(dst, src);
        }
    };

    float d[2][8][4];
    #pragma unroll
    for (int mi = 0; mi < 2; ++mi)
        #pragma unroll
        for (int f = 0; f < 8; ++f)
            #pragma unroll
            for (int e = 0; e < 4; ++e) d[mi][f][e] = 0.0f;

    // ---- prologue -----------------------------------------------------------
    ldg_A(0);
    cp_B(0, 0);
    CP_COMMIT();
    sts_A(0);

    // ---- main loop ----------------------------------------------------------
    #pragma unroll 1
    for (int i = 0; i < NCHUNK; ++i) {
        const int buf = i & 1;
        CP_WAIT0();
        __syncthreads();                       // A(i), B(i) visible

        if (i < NCHUNK - 1) {
            ldg_A(i + 1);
            cp_B(i + 1, buf ^ 1);
            CP_COMMIT();
        }

        {
            const uint32_t aoff = (uint32_t)buf * A_BUF_BY;
            const uint32_t boff = (uint32_t)buf * B_BUF_BY;
            #pragma unroll
            for (int kk = 0; kk < 4; ++kk) {
                uint32_t a[2][4];
                #pragma unroll
                for (int mi = 0; mi < 2; ++mi)
                    LDSM4(a[mi], a_addr[mi] + aoff + kk * 32);
                #pragma unroll
                for (int f16 = 0; f16 < 4; ++f16) {
                    uint32_t bfr[4];
                    LDSM4(bfr, b_addr[f16] + boff + kk * 32);
                    #pragma unroll
                    for (int mi = 0; mi < 2; ++mi) {
                        MMA16816(d[mi][2*f16],     a[mi][0], a[mi][1], a[mi][2], a[mi][3],
                                 bfr[0], bfr[1]);
                        MMA16816(d[mi][2*f16 + 1], a[mi][0], a[mi][1], a[mi][2], a[mi][3],
                                 bfr[2], bfr[3]);
                    }
                }
            }
        }

        if (i < NCHUNK - 1) sts_A(buf ^ 1);    // published by next-iter barrier
    }

    // ---- epilogue: bias + relu + store -------------------------------------
    #pragma unroll
    for (int mi = 0; mi < 2; ++mi) {
        #pragma unroll
        for (int h2 = 0; h2 < 2; ++h2) {
            const int pxe = warp_px + mi * 16 + gr + 8 * h2;
            const int Pe  = blockIdx.x * CTA_M + pxe;
            const int be  = Pe / HWSZ;
            const int hwe = Pe - be * HWSZ;
            float* ob = out + (size_t)be * COUT * HWSZ + hwe;
            #pragma unroll
            for (int f = 0; f < 8; ++f) {
                const int o = warp_n + f * 8 + lq * 2;
                const float2 bi = *(const float2*)&sbias[o];
                float v0 = d[mi][f][h2 * 2 + 0] + bi.x;
                float v1 = d[mi][f][h2 * 2 + 1] + bi.y;
                ob[(size_t)o       * HWSZ] = fmaxf(v0, 0.0f);
                ob[(size_t)(o + 1) * HWSZ] = fmaxf(v1, 0.0f);
            }
        }
    }
}

// ============================================================================
extern "C" void kernel_launch(void* const* d_in, const int* in_sizes, int n_in,
                              void* d_out, int out_size) {
    const float* x     = (const float*)d_in[0];
    const float* pw    = (const float*)d_in[1];
    const float* gamma = (const float*)d_in[2];
    const float* beta  = (const float*)d_in[3];
    const float* rmean = (const float*)d_in[4];
    const float* rvar  = (const float*)d_in[5];
    float* out = (float*)d_out;

    static bool attr_set = false;
    if (!attr_set) {
        cudaFuncSetAttribute(shiftconv_kernel,
                             cudaFuncAttributeMaxDynamicSharedMemorySize, SMEM_BYTES);
        attr_set = true;
    }

    prep_kernel<<<COUT, 64>>>(pw, gamma, beta, rmean, rvar);
    shiftconv_kernel<<<GRID, 256, SMEM_BYTES>>>(x, out);
}

// round 6
// speedup vs baseline: 1.4103x; 1.4103x over previous
#include <cuda_runtime.h>
#include <cuda_fp16.h>
#include <cstdint>

// ============================================================================
// x[32,256,56,56] -> shift2d -> 1x1 conv W[256,256] -> BN -> ReLU
// GEMM: M = 100352 pixels, N = 256, K = 256.
// mma.sync.m16n8k16 fp16 / fp32 accum, single-pass fp16 (BN folded into W).
// 256 threads, 2 CTAs/SM. Batched ldmatrix.x4 + XOR-swizzled 128B rows.
// ============================================================================
#define CIN    256
#define COUT   256
#define HH     56
#define WWD    56
#define HWSZ   3136
#define NPIX   100352          // 32*3136
#define CTA_M  64
#define GRID   (NPIX / CTA_M)  // 1568
#define KCH    64
#define NCHUNK 4

// SMEM layout (bytes):
//   [0,1024)          bias[256] f32
//   [1024, +16384)    A[buf][64 rows][128B]   XOR-unit swizzled
//   [17408, +65536)   B[buf][256 rows][128B]  XOR-unit swizzled
#define OFF_A      1024
#define OFF_B      17408
#define A_BUF_BY   8192
#define B_BUF_BY   32768
#define SMEM_BYTES 82944

// device-global scratch (sanctioned)
__device__ __half g_w[COUT * CIN];    // W[o][c] * inv[o], fp16, k-contiguous
__device__ float  g_bias[COUT];

#define DEVINL __device__ __forceinline__

DEVINL uint32_t smem_u32(const void* p) {
    uint32_t a;
    asm("{ .reg .u64 t; cvta.to.shared.u64 t, %1; cvt.u32.u64 %0, t; }"
        : "=r"(a) : "l"(p));
    return a;
}

#define CP_ASYNC16(dst_u32, src_ptr) \
    asm volatile("cp.async.cg.shared.global [%0], [%1], 16;" \
        :: "r"(dst_u32), "l"(src_ptr) : "memory")
#define CP_COMMIT() asm volatile("cp.async.commit_group;" ::: "memory")
#define CP_WAIT0()  asm volatile("cp.async.wait_group 0;"  ::: "memory")

#define MMA16816(d, a0, a1, a2, a3, b0, b1) \
    asm volatile("mma.sync.aligned.m16n8k16.row.col.f32.f16.f16.f32 " \
        "{%0,%1,%2,%3}, {%4,%5,%6,%7}, {%8,%9}, {%0,%1,%2,%3};" \
        : "+f"((d)[0]), "+f"((d)[1]), "+f"((d)[2]), "+f"((d)[3]) \
        : "r"(a0), "r"(a1), "r"(a2), "r"(a3), "r"(b0), "r"(b1))

#define LDSM4(r, addr) \
    asm volatile("ldmatrix.sync.aligned.m8n8.x4.shared.b16 {%0,%1,%2,%3}, [%4];" \
        : "=r"((r)[0]), "=r"((r)[1]), "=r"((r)[2]), "=r"((r)[3]) : "r"(addr))

#define STS128(addr, v) \
    asm volatile("st.shared.v4.b32 [%0], {%1,%2,%3,%4};" \
        :: "r"(addr), "r"((v).x), "r"((v).y), "r"((v).z), "r"((v).w) : "memory")

// channel -> shift direction index (group starts: 0,51,102,153,204)
DEVINL int ch_dir(int c) {
    return (c >= 204) ? 4 : (c >= 153) ? 3 : (c >= 102) ? 2 : (c >= 51) ? 1 : 0;
}

// ============================================================================
// prep: fold BN scale into W, convert to fp16; compute bias.
// ============================================================================
__global__ void prep_kernel(const float* __restrict__ pw,
                            const float* __restrict__ gamma,
                            const float* __restrict__ beta,
                            const float* __restrict__ rmean,
                            const float* __restrict__ rvar)
{
    const int o  = blockIdx.x;
    const int c4 = threadIdx.x;            // 0..63, handles 4 channels
    const float inv_o = gamma[o] * rsqrtf(rvar[o] + 1e-5f);
    float4 v = *reinterpret_cast<const float4*>(pw + (size_t)o * CIN + c4 * 4);
    __half2 h01 = __floats2half2_rn(v.x * inv_o, v.y * inv_o);
    __half2 h23 = __floats2half2_rn(v.z * inv_o, v.w * inv_o);
    *reinterpret_cast<__half2*>(g_w + (size_t)o * CIN + c4 * 4)     = h01;
    *reinterpret_cast<__half2*>(g_w + (size_t)o * CIN + c4 * 4 + 2) = h23;
    if (o == 0) {
        #pragma unroll
        for (int j = 0; j < 4; ++j) {
            int c = c4 * 4 + j;
            float inv_c = gamma[c] * rsqrtf(rvar[c] + 1e-5f);
            g_bias[c] = beta[c] - rmean[c] * inv_c;
        }
    }
}

// ============================================================================
// main kernel: 256 threads, warp grid 2(M) x 4(N); warp tile 32 x 64.
// ============================================================================
__global__ void __launch_bounds__(256, 2)
shiftconv_kernel(const float* __restrict__ x, float* __restrict__ out)
{
    extern __shared__ char smem[];
    float* sbias = (float*)smem;

    const int tid  = threadIdx.x;
    const int warp = tid >> 5;
    const int lane = tid & 31;
    const int gr   = lane >> 2;
    const int lq   = lane & 3;

    const int warp_px = (warp & 1) * 32;   // M offset within CTA
    const int warp_n  = (warp >> 1) * 64;  // N offset

    sbias[tid] = g_bias[tid];

    const uint32_t sA_u32 = smem_u32(smem + OFF_A);
    const uint32_t sB_u32 = smem_u32(smem + OFF_B);

    // ---- ldmatrix per-lane bases (XOR-unit swizzle folded per kk) ----------
    // A: tiles rows0-7/k0-7, rows8-15/k0-7, rows0-7/k8-15, rows8-15/k8-15
    uint32_t a_base[2];
    const uint32_t a_c  = (uint32_t)(lane >> 4);        // k 16B-unit half
    const uint32_t a_x7 = (uint32_t)(lane & 7);         // row&7 for swizzle
    {
        const int arow = lane & 15;
        #pragma unroll
        for (int mi = 0; mi < 2; ++mi)
            a_base[mi] = sA_u32 + (uint32_t)(warp_px + mi * 16 + arow) * 128;
    }
    // B: per 16-row n-tile: lanes0-7 n0-7/k0-7, 8-15 n0-7/k8-15,
    //    16-23 n8-15/k0-7, 24-31 n8-15/k8-15
    uint32_t b_base[4];
    const int grp = lane >> 3;
    const int nrow = lane - ((grp == 1 || grp == 2) ? 8 : (grp == 3) ? 16 : 0);
    const uint32_t b_c  = (uint32_t)(grp & 1);
    const uint32_t b_x7 = (uint32_t)(nrow & 7);
    #pragma unroll
    for (int f16 = 0; f16 < 4; ++f16)
        b_base[f16] = sB_u32 + (uint32_t)(warp_n + f16 * 16 + nrow) * 128;

    // ---- A staging thread mapping ------------------------------------------
    const int pxl = tid & 63;
    const int c2  = tid >> 6;
    const int P   = blockIdx.x * CTA_M + pxl;
    const int bb  = P / HWSZ;
    const int rr  = P - bb * HWSZ;
    const int hh  = rr / WWD;
    const int ww  = rr - hh * WWD;
    const float* xb = x + (size_t)bb * CIN * HWSZ;

    int  offs[5];
    bool vald[5];
    {
        const int dxs[5] = {0, 1, -1, 0, 0};
        const int dys[5] = {0, 0, 0, 1, -1};
        #pragma unroll
        for (int d5 = 0; d5 < 5; ++d5) {
            int hs = hh - dys[d5], ws = ww - dxs[d5];
            vald[d5] = ((unsigned)hs < HH) && ((unsigned)ws < WWD);
            offs[d5] = hs * WWD + ws;
        }
    }
    // staging store addresses (swizzled, computed once)
    const uint32_t a_st0 = sA_u32 + (uint32_t)pxl * 128 +
                           ((((uint32_t)c2 * 2)     ^ (uint32_t)(pxl & 7)) << 4);
    const uint32_t a_st1 = sA_u32 + (uint32_t)pxl * 128 +
                           ((((uint32_t)c2 * 2 + 1) ^ (uint32_t)(pxl & 7)) << 4);

    // B staging mapping
    const int bu = tid & 7;
    const int bn = tid >> 3;
    const uint32_t b_st = sB_u32 + (uint32_t)bn * 128 +
                          (((uint32_t)bu ^ (uint32_t)(bn & 7)) << 4);

    uint32_t hstage[8];       // 16 channels as packed half2

    auto ldg_A = [&](int chunk) {
        const int c0 = chunk * KCH;
        #pragma unroll
        for (int it = 0; it < 8; ++it) {
            const int ch0 = c0 + 2 * (c2 * 8 + it);
            const int d0  = ch_dir(ch0);
            const int d1  = ch_dir(ch0 + 1);
            float v0 = vald[d0] ? __ldg(xb + (size_t)ch0       * HWSZ + offs[d0]) : 0.0f;
            float v1 = vald[d1] ? __ldg(xb + (size_t)(ch0 + 1) * HWSZ + offs[d1]) : 0.0f;
            __half2 h = __floats2half2_rn(v0, v1);
            hstage[it] = *reinterpret_cast<uint32_t*>(&h);
        }
    };

    auto sts_A = [&](int buf) {
        const uint32_t o = (uint32_t)buf * A_BUF_BY;
        uint4 u0 = make_uint4(hstage[0], hstage[1], hstage[2], hstage[3]);
        uint4 u1 = make_uint4(hstage[4], hstage[5], hstage[6], hstage[7]);
        STS128(a_st0 + o, u0);
        STS128(a_st1 + o, u1);
    };

    auto cp_B = [&](int chunk, int buf) {
        const int c0 = chunk * KCH;
        #pragma unroll
        for (int itn = 0; itn < 8; ++itn) {
            const int n = bn + 32 * itn;
            const uint32_t dst = b_st + (uint32_t)(buf * 256 + 32 * itn) * 128;
            const __half* src = g_w + (size_t)n * CIN + c0 + bu * 8;
            CP_ASYNC16(dst, src);
        }
    };

    float d[2][8][4];
    #pragma unroll
    for (int mi = 0; mi < 2; ++mi)
        #pragma unroll
        for (int f = 0; f < 8; ++f)
            #pragma unroll
            for (int e = 0; e < 4; ++e) d[mi][f][e] = 0.0f;

    // ---- prologue -----------------------------------------------------------
    ldg_A(0);
    cp_B(0, 0);
    CP_COMMIT();
    sts_A(0);

    // ---- main loop ----------------------------------------------------------
    #pragma unroll 1
    for (int i = 0; i < NCHUNK; ++i) {
        const int buf = i & 1;
        CP_WAIT0();
        __syncthreads();                       // A(i), B(i) visible

        if (i < NCHUNK - 1) {
            ldg_A(i + 1);
            cp_B(i + 1, buf ^ 1);
            CP_COMMIT();
        }

        {
            const uint32_t aoff = (uint32_t)buf * A_BUF_BY;
            const uint32_t boff = (uint32_t)buf * B_BUF_BY;
            #pragma unroll
            for (int kk = 0; kk < 4; ++kk) {
                // batched fragment loads: 6 LDSM issued back-to-back (MLP)
                uint32_t a[2][4], b[4][4];
                #pragma unroll
                for (int mi = 0; mi < 2; ++mi)
                    LDSM4(a[mi], a_base[mi] + aoff +
                          ((((uint32_t)(2 * kk) + a_c) ^ a_x7) << 4));
                #pragma unroll
                for (int f16 = 0; f16 < 4; ++f16)
                    LDSM4(b[f16], b_base[f16] + boff +
                          ((((uint32_t)(2 * kk) + b_c) ^ b_x7) << 4));
                #pragma unroll
                for (int f16 = 0; f16 < 4; ++f16)
                    #pragma unroll
                    for (int mi = 0; mi < 2; ++mi) {
                        MMA16816(d[mi][2*f16],     a[mi][0], a[mi][1], a[mi][2], a[mi][3],
                                 b[f16][0], b[f16][1]);
                        MMA16816(d[mi][2*f16 + 1], a[mi][0], a[mi][1], a[mi][2], a[mi][3],
                                 b[f16][2], b[f16][3]);
                    }
            }
        }

        if (i < NCHUNK - 1) sts_A(buf ^ 1);    // published by next-iter barrier
    }

    // ---- epilogue: bias + relu + store -------------------------------------
    #pragma unroll
    for (int mi = 0; mi < 2; ++mi) {
        #pragma unroll
        for (int h2 = 0; h2 < 2; ++h2) {
            const int pxe = warp_px + mi * 16 + gr + 8 * h2;
            const int Pe  = blockIdx.x * CTA_M + pxe;
            const int be  = Pe / HWSZ;
            const int hwe = Pe - be * HWSZ;
            float* ob = out + (size_t)be * COUT * HWSZ + hwe;
            #pragma unroll
            for (int f = 0; f < 8; ++f) {
                const int o = warp_n + f * 8 + lq * 2;
                const float2 bi = *(const float2*)&sbias[o];
                float v0 = d[mi][f][h2 * 2 + 0] + bi.x;
                float v1 = d[mi][f][h2 * 2 + 1] + bi.y;
                ob[(size_t)o       * HWSZ] = fmaxf(v0, 0.0f);
                ob[(size_t)(o + 1) * HWSZ] = fmaxf(v1, 0.0f);
            }
        }
    }
}

// ============================================================================
extern "C" void kernel_launch(void* const* d_in, const int* in_sizes, int n_in,
                              void* d_out, int out_size) {
    const float* x     = (const float*)d_in[0];
    const float* pw    = (const float*)d_in[1];
    const float* gamma = (const float*)d_in[2];
    const float* beta  = (const float*)d_in[3];
    const float* rmean = (const float*)d_in[4];
    const float* rvar  = (const float*)d_in[5];
    float* out = (float*)d_out;

    static bool attr_set = false;
    if (!attr_set) {
        cudaFuncSetAttribute(shiftconv_kernel,
                             cudaFuncAttributeMaxDynamicSharedMemorySize, SMEM_BYTES);
        attr_set = true;
    }

    prep_kernel<<<COUT, 64>>>(pw, gamma, beta, rmean, rvar);
    shiftconv_kernel<<<GRID, 256, SMEM_BYTES>>>(x, out);
}

// round 7
// speedup vs baseline: 1.5463x; 1.0965x over previous
#include <cuda_runtime.h>
#include <cuda_fp16.h>
#include <cstdint>

// ============================================================================
// x[32,256,56,56] -> shift2d -> 1x1 conv W[256,256] -> BN -> ReLU
// GEMM: M = 100352 pixels, N = 256, K = 256.
// mma.sync.m16n8k16 fp16 / fp32 accum, single-pass fp16 (BN folded into W).
// 256 threads, 2 CTAs/SM. Batched ldmatrix.x4 + XOR-swizzled 128B rows.
// R6: A-staging pipelined one iteration ahead (STS decoupled from barrier).
// ============================================================================
#define CIN    256
#define COUT   256
#define HH     56
#define WWD    56
#define HWSZ   3136
#define NPIX   100352          // 32*3136
#define CTA_M  64
#define GRID   (NPIX / CTA_M)  // 1568
#define KCH    64
#define NCHUNK 4

// SMEM layout (bytes):
//   [0,1024)          bias[256] f32
//   [1024, +16384)    A[buf][64 rows][128B]   XOR-unit swizzled
//   [17408, +65536)   B[buf][256 rows][128B]  XOR-unit swizzled
#define OFF_A      1024
#define OFF_B      17408
#define A_BUF_BY   8192
#define B_BUF_BY   32768
#define SMEM_BYTES 82944

// device-global scratch (sanctioned)
__device__ __half g_w[COUT * CIN];    // W[o][c] * inv[o], fp16, k-contiguous
__device__ float  g_bias[COUT];

#define DEVINL __device__ __forceinline__

DEVINL uint32_t smem_u32(const void* p) {
    uint32_t a;
    asm("{ .reg .u64 t; cvta.to.shared.u64 t, %1; cvt.u32.u64 %0, t; }"
        : "=r"(a) : "l"(p));
    return a;
}

#define CP_ASYNC16(dst_u32, src_ptr) \
    asm volatile("cp.async.cg.shared.global [%0], [%1], 16;" \
        :: "r"(dst_u32), "l"(src_ptr) : "memory")
#define CP_COMMIT() asm volatile("cp.async.commit_group;" ::: "memory")
#define CP_WAIT0()  asm volatile("cp.async.wait_group 0;"  ::: "memory")

#define MMA16816(d, a0, a1, a2, a3, b0, b1) \
    asm volatile("mma.sync.aligned.m16n8k16.row.col.f32.f16.f16.f32 " \
        "{%0,%1,%2,%3}, {%4,%5,%6,%7}, {%8,%9}, {%0,%1,%2,%3};" \
        : "+f"((d)[0]), "+f"((d)[1]), "+f"((d)[2]), "+f"((d)[3]) \
        : "r"(a0), "r"(a1), "r"(a2), "r"(a3), "r"(b0), "r"(b1))

#define LDSM4(r, addr) \
    asm volatile("ldmatrix.sync.aligned.m8n8.x4.shared.b16 {%0,%1,%2,%3}, [%4];" \
        : "=r"((r)[0]), "=r"((r)[1]), "=r"((r)[2]), "=r"((r)[3]) : "r"(addr))

#define STS128(addr, v) \
    asm volatile("st.shared.v4.b32 [%0], {%1,%2,%3,%4};" \
        :: "r"(addr), "r"((v).x), "r"((v).y), "r"((v).z), "r"((v).w) : "memory")

// channel -> shift direction index (group starts: 0,51,102,153,204)
DEVINL int ch_dir(int c) {
    return (c >= 204) ? 4 : (c >= 153) ? 3 : (c >= 102) ? 2 : (c >= 51) ? 1 : 0;
}

// ============================================================================
// prep: fold BN scale into W, convert to fp16; compute bias.
// ============================================================================
__global__ void prep_kernel(const float* __restrict__ pw,
                            const float* __restrict__ gamma,
                            const float* __restrict__ beta,
                            const float* __restrict__ rmean,
                            const float* __restrict__ rvar)
{
    const int o  = blockIdx.x;
    const int c4 = threadIdx.x;            // 0..63, handles 4 channels
    const float inv_o = gamma[o] * rsqrtf(rvar[o] + 1e-5f);
    float4 v = *reinterpret_cast<const float4*>(pw + (size_t)o * CIN + c4 * 4);
    __half2 h01 = __floats2half2_rn(v.x * inv_o, v.y * inv_o);
    __half2 h23 = __floats2half2_rn(v.z * inv_o, v.w * inv_o);
    *reinterpret_cast<__half2*>(g_w + (size_t)o * CIN + c4 * 4)     = h01;
    *reinterpret_cast<__half2*>(g_w + (size_t)o * CIN + c4 * 4 + 2) = h23;
    if (o == 0) {
        #pragma unroll
        for (int j = 0; j < 4; ++j) {
            int c = c4 * 4 + j;
            float inv_c = gamma[c] * rsqrtf(rvar[c] + 1e-5f);
            g_bias[c] = beta[c] - rmean[c] * inv_c;
        }
    }
}

// ============================================================================
// main kernel: 256 threads, warp grid 2(M) x 4(N); warp tile 32 x 64.
// ============================================================================
__global__ void __launch_bounds__(256, 2)
shiftconv_kernel(const float* __restrict__ x, float* __restrict__ out)
{
    extern __shared__ char smem[];
    float* sbias = (float*)smem;

    const int tid  = threadIdx.x;
    const int warp = tid >> 5;
    const int lane = tid & 31;
    const int gr   = lane >> 2;
    const int lq   = lane & 3;

    const int warp_px = (warp & 1) * 32;   // M offset within CTA
    const int warp_n  = (warp >> 1) * 64;  // N offset

    sbias[tid] = g_bias[tid];

    const uint32_t sA_u32 = smem_u32(smem + OFF_A);
    const uint32_t sB_u32 = smem_u32(smem + OFF_B);

    // ---- ldmatrix per-lane bases (XOR-unit swizzle folded per kk) ----------
    uint32_t a_base[2];
    const uint32_t a_c  = (uint32_t)(lane >> 4);        // k 16B-unit half
    const uint32_t a_x7 = (uint32_t)(lane & 7);         // row&7 for swizzle
    {
        const int arow = lane & 15;
        #pragma unroll
        for (int mi = 0; mi < 2; ++mi)
            a_base[mi] = sA_u32 + (uint32_t)(warp_px + mi * 16 + arow) * 128;
    }
    uint32_t b_base[4];
    const int grp = lane >> 3;
    const int nrow = lane - ((grp == 1 || grp == 2) ? 8 : (grp == 3) ? 16 : 0);
    const uint32_t b_c  = (uint32_t)(grp & 1);
    const uint32_t b_x7 = (uint32_t)(nrow & 7);
    #pragma unroll
    for (int f16 = 0; f16 < 4; ++f16)
        b_base[f16] = sB_u32 + (uint32_t)(warp_n + f16 * 16 + nrow) * 128;

    // ---- A staging thread mapping ------------------------------------------
    const int pxl = tid & 63;
    const int c2  = tid >> 6;
    const int P   = blockIdx.x * CTA_M + pxl;
    const int bb  = P / HWSZ;
    const int rr  = P - bb * HWSZ;
    const int hh  = rr / WWD;
    const int ww  = rr - hh * WWD;
    const float* xb = x + (size_t)bb * CIN * HWSZ;

    int  offs[5];
    bool vald[5];
    {
        const int dxs[5] = {0, 1, -1, 0, 0};
        const int dys[5] = {0, 0, 0, 1, -1};
        #pragma unroll
        for (int d5 = 0; d5 < 5; ++d5) {
            int hs = hh - dys[d5], ws = ww - dxs[d5];
            vald[d5] = ((unsigned)hs < HH) && ((unsigned)ws < WWD);
            offs[d5] = hs * WWD + ws;
        }
    }
    const uint32_t a_st0 = sA_u32 + (uint32_t)pxl * 128 +
                           ((((uint32_t)c2 * 2)     ^ (uint32_t)(pxl & 7)) << 4);
    const uint32_t a_st1 = sA_u32 + (uint32_t)pxl * 128 +
                           ((((uint32_t)c2 * 2 + 1) ^ (uint32_t)(pxl & 7)) << 4);

    // B staging mapping
    const int bu = tid & 7;
    const int bn = tid >> 3;
    const uint32_t b_st = sB_u32 + (uint32_t)bn * 128 +
                          (((uint32_t)bu ^ (uint32_t)(bn & 7)) << 4);

    uint32_t hstage[8];       // 16 channels as packed half2 (one chunk ahead+1)

    auto ldg_A = [&](int chunk) {
        const int c0 = chunk * KCH;
        #pragma unroll
        for (int it = 0; it < 8; ++it) {
            const int ch0 = c0 + 2 * (c2 * 8 + it);
            const int d0  = ch_dir(ch0);
            const int d1  = ch_dir(ch0 + 1);
            float v0 = vald[d0] ? __ldg(xb + (size_t)ch0       * HWSZ + offs[d0]) : 0.0f;
            float v1 = vald[d1] ? __ldg(xb + (size_t)(ch0 + 1) * HWSZ + offs[d1]) : 0.0f;
            __half2 h = __floats2half2_rn(v0, v1);
            hstage[it] = *reinterpret_cast<uint32_t*>(&h);
        }
    };

    auto sts_A = [&](int buf) {
        const uint32_t o = (uint32_t)buf * A_BUF_BY;
        uint4 u0 = make_uint4(hstage[0], hstage[1], hstage[2], hstage[3]);
        uint4 u1 = make_uint4(hstage[4], hstage[5], hstage[6], hstage[7]);
        STS128(a_st0 + o, u0);
        STS128(a_st1 + o, u1);
    };

    auto cp_B = [&](int chunk, int buf) {
        const int c0 = chunk * KCH;
        #pragma unroll
        for (int itn = 0; itn < 8; ++itn) {
            const int n = bn + 32 * itn;
            const uint32_t dst = b_st + (uint32_t)(buf * 256 + 32 * itn) * 128;
            const __half* src = g_w + (size_t)n * CIN + c0 + bu * 8;
            CP_ASYNC16(dst, src);
        }
    };

    float d[2][8][4];
    #pragma unroll
    for (int mi = 0; mi < 2; ++mi)
        #pragma unroll
        for (int f = 0; f < 8; ++f)
            #pragma unroll
            for (int e = 0; e < 4; ++e) d[mi][f][e] = 0.0f;

    // ---- prologue: chunk0 fully staged, chunk1 LDG in flight ---------------
    ldg_A(0);
    cp_B(0, 0);
    CP_COMMIT();
    sts_A(0);           // hstage(0) -> bufA 0
    ldg_A(1);           // hstage <- chunk 1 (lands during iter 0)

    // ---- main loop ----------------------------------------------------------
    // iter i: wait B(i); barrier publishes A(i)/B(i) and frees the other bufs;
    //         STS A(i+1) (data LDG'd at iter i-1) -> buf !(i&1)   [disjoint]
    //         LDG A(i+2) -> hstage; cp_B(i+1)+commit; compute(i)
    #pragma unroll 1
    for (int i = 0; i < NCHUNK; ++i) {
        const int buf = i & 1;
        CP_WAIT0();
        __syncthreads();                       // A(i), B(i) visible

        if (i < NCHUNK - 1) sts_A(buf ^ 1);    // A(i+1), full compute of slack
        if (i < NCHUNK - 2) ldg_A(i + 2);      // long-latency loads, 1 iter early
        if (i < NCHUNK - 1) {
            cp_B(i + 1, buf ^ 1);
            CP_COMMIT();
        }

        {
            const uint32_t aoff = (uint32_t)buf * A_BUF_BY;
            const uint32_t boff = (uint32_t)buf * B_BUF_BY;
            #pragma unroll
            for (int kk = 0; kk < 4; ++kk) {
                uint32_t a[2][4], b[4][4];
                #pragma unroll
                for (int mi = 0; mi < 2; ++mi)
                    LDSM4(a[mi], a_base[mi] + aoff +
                          ((((uint32_t)(2 * kk) + a_c) ^ a_x7) << 4));
                #pragma unroll
                for (int f16 = 0; f16 < 4; ++f16)
                    LDSM4(b[f16], b_base[f16] + boff +
                          ((((uint32_t)(2 * kk) + b_c) ^ b_x7) << 4));
                #pragma unroll
                for (int f16 = 0; f16 < 4; ++f16)
                    #pragma unroll
                    for (int mi = 0; mi < 2; ++mi) {
                        MMA16816(d[mi][2*f16],     a[mi][0], a[mi][1], a[mi][2], a[mi][3],
                                 b[f16][0], b[f16][1]);
                        MMA16816(d[mi][2*f16 + 1], a[mi][0], a[mi][1], a[mi][2], a[mi][3],
                                 b[f16][2], b[f16][3]);
                    }
            }
        }
    }

    // ---- epilogue: bias + relu + store -------------------------------------
    #pragma unroll
    for (int mi = 0; mi < 2; ++mi) {
        #pragma unroll
        for (int h2 = 0; h2 < 2; ++h2) {
            const int pxe = warp_px + mi * 16 + gr + 8 * h2;
            const int Pe  = blockIdx.x * CTA_M + pxe;
            const int be  = Pe / HWSZ;
            const int hwe = Pe - be * HWSZ;
            float* ob = out + (size_t)be * COUT * HWSZ + hwe;
            #pragma unroll
            for (int f = 0; f < 8; ++f) {
                const int o = warp_n + f * 8 + lq * 2;
                const float2 bi = *(const float2*)&sbias[o];
                float v0 = d[mi][f][h2 * 2 + 0] + bi.x;
                float v1 = d[mi][f][h2 * 2 + 1] + bi.y;
                ob[(size_t)o       * HWSZ] = fmaxf(v0, 0.0f);
                ob[(size_t)(o + 1) * HWSZ] = fmaxf(v1, 0.0f);
            }
        }
    }
}

// ============================================================================
extern "C" void kernel_launch(void* const* d_in, const int* in_sizes, int n_in,
                              void* d_out, int out_size) {
    const float* x     = (const float*)d_in[0];
    const float* pw    = (const float*)d_in[1];
    const float* gamma = (const float*)d_in[2];
    const float* beta  = (const float*)d_in[3];
    const float* rmean = (const float*)d_in[4];
    const float* rvar  = (const float*)d_in[5];
    float* out = (float*)d_out;

    static bool attr_set = false;
    if (!attr_set) {
        cudaFuncSetAttribute(shiftconv_kernel,
                             cudaFuncAttributeMaxDynamicSharedMemorySize, SMEM_BYTES);
        attr_set = true;
    }

    prep_kernel<<<COUT, 64>>>(pw, gamma, beta, rmean, rvar);
    shiftconv_kernel<<<GRID, 256, SMEM_BYTES>>>(x, out);
}